// round 12
// baseline (speedup 1.0000x reference)
#include <cuda_runtime.h>

constexpr int kB = 32;
constexpr int kA = 5;
constexpr int kC = 8;
constexpr int kH = 32;
constexpr int kW = 64;
constexpr int kT = 50;
constexpr int kCh = 7 + kC;                 // 15
constexpr int kHW = kH * kW;                // 2048
constexpr int kBlocksPerB = 40;             // anchor(5) x rowgroup(4 of 8 rows) x colhalf(2 of 32 cols)
constexpr int kGrid = kB * kBlocksPerB;     // 1280

__constant__ float c_aw[kA] = {1.08f, 3.42f, 6.63f, 9.42f, 16.62f};
__constant__ float c_al[kA] = {1.19f, 4.41f, 11.38f, 5.11f, 10.52f};

__device__ float        g_partials[kGrid];
__device__ unsigned int g_count = 0;   // self-resets -> graph-replay deterministic

__shared__ float4   cbox[kT];          // {x1, 1.6*y1, x2, 1.6*y2}
__shared__ float    cna[kT];           // -0.6 * target area
__shared__ float2   sxw[kT];           // x-window {txc - tw/3 - eps, txc + tw/3 + eps}
__shared__ float2   syw[kT];           // y-window {tyc - tl/3 - eps, tyc + tl/3 + eps}
__shared__ float    std_[kT][12];      // tx,ty,tw,tl,tim,tre,tcls, x1,y1s,x2,y2s
__shared__ int      s_map[256];        // block-local cell -> winning target
__shared__ unsigned s_mask[2];
__shared__ int      s_cnt;
__shared__ float    wred[8];
__shared__ bool     s_last;

// matched-cell loss (rare: <=50 cells/batch; spills here are acceptable)
__device__ __forceinline__ float matched_loss(
    int map, const float* __restrict__ base,
    float sxv, float syv, float conf, float c2, float c3,
    float x1, float x2, float y1s, float y2s, float parea)
{
    float c4 = base[4 * kHW];
    float c5 = base[5 * kHW];
    float dx   = sxv - std_[map][0];
    float dy   = syv - std_[map][1];
    float dw   = c2  - std_[map][2];
    float dl   = c3  - std_[map][3];
    float dim_ = c4  - std_[map][4];
    float dre  = c5  - std_[map][5];

    float bx1 = std_[map][7], by1s = std_[map][8];
    float bx2 = std_[map][9], by2s = std_[map][10];
    float cw  = fminf(x2, bx2) - fmaxf(x1, bx1);
    float chs = fminf(y2s, by2s) - fmaxf(y1s, by1s);
    float inter = fmaxf(cw, 0.0f) * fmaxf(chs, 0.0f) * 0.625f;
    float tgw = bx2 - bx1;
    float tgl = (by2s - by1s) * 0.625f;
    float uni = parea + tgw * tgl - inter;
    float tconf = inter / uni;
    float dconf = conf * 10.0f - tconf * 10.0f;

    float cl[kC];
#pragma unroll
    for (int q = 0; q < kC; q++) cl[q] = base[(size_t)(7 + q) * kHW];
    float mx = cl[0];
#pragma unroll
    for (int q = 1; q < kC; q++) mx = fmaxf(mx, cl[q]);
    float s = 0.0f;
#pragma unroll
    for (int q = 0; q < kC; q++) s += __expf(cl[q] - mx);
    int tcls = (int)std_[map][6];
    float ce = mx + logf(s) - cl[tcls];

    return dx * dx + dy * dy + dw * dw + dl * dl + dim_ * dim_ + dre * dre
         + dconf * dconf + ce;
}

__global__ void __launch_bounds__(256, 8) k_fused(const float* __restrict__ out,
                                                  const float* __restrict__ tgt,
                                                  float* __restrict__ loss,
                                                  int out_size) {
    const int tid = threadIdx.x;
    const int bid = blockIdx.x;
    const int b   = bid / kBlocksPerB;
    const int cb  = bid - b * kBlocksPerB;
    const int a   = cb >> 3;                       // anchor
    const int rg  = (cb >> 1) & 3;                 // 8-row group
    const int chf = cb & 1;                        // 32-col half
    const int rowbase = rg << 3;
    const int colbase = chf << 5;

    // warp tiling: 16 cols x 2 rows per warp; 1 cell/thread
    const int lane = tid & 31;
    const int wrp  = tid >> 5;
    const int xT   = wrp & 1;
    const int yT   = wrp >> 1;                     // 0..3
    const int iLoc = (xT << 4) + (lane & 15);      // 0..31
    const int jLoc = (yT << 1) + (lane >> 4);      // 0..7
    const int i    = colbase + iLoc;
    const int j    = rowbase + jLoc;
    const int off0 = (jLoc << 5) + iLoc;           // s_map index
    const int rem  = (j << 6) + i;

    // hot channels (c4/c5 matched-path-only)
    const float* base = out + ((size_t)(b * kA + a) * kCh) * kHW + rem;
    float a0 = base[0 * kHW];
    float a1 = base[1 * kHW];
    float a2 = base[2 * kHW];
    float a3 = base[3 * kHW];
    float a6 = base[6 * kHW];

    // ---------------- phase 1: per-target values + masks --------------------
    s_map[tid] = -1;
    if (tid == 0) s_cnt = 0;

    const float* tr = tgt + ((size_t)b * kT + tid) * 7;
    bool validt = (tid < kT) && (tr[1] != 0.0f);
    unsigned bm = __ballot_sync(0xffffffffu, validt);
    if ((tid & 31) == 0 && tid < 64) s_mask[tid >> 5] = bm;

    float gx = 0.f, gy = 0.f, gw = 0.f, gl = 0.f, garea = 0.f;
    int gi = 0, gj = 0, besta = 0, off = -1;
    if (validt) {
        gx = tr[1] * (float)kW;
        gy = tr[2] * (float)kH;
        gw = tr[3] * (float)kW;
        gl = tr[4] * (float)kH;
        gi = min(max((int)gx, 0), kW - 1);
        gj = min(max((int)gy, 0), kH - 1);
        garea = gw * gl;

        // division-free first-max-wins anchor argmax
        float bin = fminf(gw, c_aw[0]) * fminf(gl, c_al[0]);
        float bun = garea + c_aw[0] * c_al[0] - bin;
#pragma unroll
        for (int q = 1; q < kA; q++) {
            float in_ = fminf(gw, c_aw[q]) * fminf(gl, c_al[q]);
            float un_ = garea + c_aw[q] * c_al[q] - in_;
            if (in_ * bun > bin * un_) { besta = q; bin = in_; bun = un_; }
        }
        // this block's local cell index, or -1 if the target maps elsewhere
        if (besta == a && gj >= rowbase && gj < rowbase + 8
                       && gi >= colbase && gi < colbase + 32)
            off = ((gj - rowbase) << 5) + (gi - colbase);
    }
    __syncthreads();                               // sync 1

    unsigned long long mm = (unsigned long long)s_mask[0]
                          | ((unsigned long long)s_mask[1] << 32);
    const int nv = __ffsll((long long)~mm) - 1;    // cumprod-validity prefix

    const bool inpfx = (tid < nv);
    if (inpfx) {
        if (off >= 0) atomicMax(&s_map[off], tid);
        // block-level x+y cull: IoU>0.6 needs |pxc-txc| < tw/3 and |pyc-tyc| < tl/3
        float tl3 = gl * (1.0f / 3.0f) + 1e-3f;
        float tw3 = gw * (1.0f / 3.0f) + 1e-3f;
        if (gy + tl3 > (float)rowbase && gy - tl3 < (float)(rowbase + 8) &&
            gx + tw3 > (float)colbase && gx - tw3 < (float)(colbase + 32)) {
            int p = atomicAdd(&s_cnt, 1);
            cbox[p] = make_float4(gx - gw * 0.5f, 1.6f * (gy - gl * 0.5f),
                                  gx + gw * 0.5f, 1.6f * (gy + gl * 0.5f));
            cna[p]  = -0.6f * garea;
            sxw[p] = make_float2(gx - tw3, gx + tw3);
            syw[p] = make_float2(gy - tl3, gy + tl3);
        }
    }
    __syncthreads();                               // sync 2

    // phase 2: dedupe winners write regression targets (hidden behind loop)
    if (inpfx && off >= 0 && s_map[off] == tid) {
        std_[tid][0] = gx - (float)gi;
        std_[tid][1] = gy - (float)gj;
        std_[tid][2] = logf(gw / c_aw[besta]);
        std_[tid][3] = logf(gl / c_al[besta]);
        std_[tid][4] = tr[5];
        std_[tid][5] = tr[6];
        std_[tid][6] = tr[0];
        std_[tid][7] = gx - gw * 0.5f;
        std_[tid][8] = 1.6f * (gy - gl * 0.5f);
        std_[tid][9] = gx + gw * 0.5f;
        std_[tid][10] = 1.6f * (gy + gl * 0.5f);
    }

    // ---------------- per-cell derived values -------------------------------
    float sxv  = 1.0f / (1.0f + __expf(-a0));
    float syv  = 1.0f / (1.0f + __expf(-a1));
    float conf = 1.0f / (1.0f + __expf(-a6));

    float pw = __expf(a2) * c_aw[a];
    float pl = __expf(a3) * c_al[a];
    float px = sxv + (float)i;
    float py = syv + (float)j;

    float x1 = px - pw * 0.5f, x2 = px + pw * 0.5f;
    float y1s = 1.6f * (py - pl * 0.5f), y2s = 1.6f * (py + pl * 0.5f);
    float parea = pw * pl;
    float th = 0.6f * parea;

    // ---------------- per-warp x/y culling bitmask --------------------------
    // Warp spans cols [colLo, colLo+16), rows [rowLo, rowLo+2).
    const int nc = s_cnt;
    const float colLo = (float)(colbase + (xT << 4));
    const float rowLo = (float)(rowbase + (yT << 1));
    unsigned mk0, mk1;
    {
        bool p0 = false, p1 = false;
        if (lane < nc) {
            float2 xw = sxw[lane];
            float2 yw = syw[lane];
            p0 = (xw.y > colLo) && (xw.x < colLo + 16.0f)
              && (yw.y > rowLo) && (yw.x < rowLo + 2.0f);
        }
        int l2 = lane + 32;
        if (l2 < nc) {
            float2 xw = sxw[l2];
            float2 yw = syw[l2];
            p1 = (xw.y > colLo) && (xw.x < colLo + 16.0f)
              && (yw.y > rowLo) && (yw.x < rowLo + 2.0f);
        }
        mk0 = __ballot_sync(0xffffffffu, p0);
        mk1 = __ballot_sync(0xffffffffu, p1);
    }

    // ---------------- exists(iou > 0.6) over bitmask survivors --------------
    float m0 = -1e30f;
    unsigned m = mk0;
    int basebit = 0;
#pragma unroll 2
    for (int half = 0; half < 2; half++) {
        while (m) {
            int t = basebit + __ffs(m) - 1;
            m &= m - 1;
            float4 q = cbox[t];
            float  n = cna[t];
            float cw = fminf(x2, q.z) - fmaxf(x1, q.x);
            float ch = fminf(y2s, q.w) - fmaxf(y1s, q.y);
            m0 = fmaxf(m0, fmaf(fmaxf(cw, 0.0f), ch, n));
        }
        m = mk1;
        basebit = 32;
    }
    bool found = m0 > th;

    __syncthreads();                               // sync 3: std_ visible
    const int map = s_map[off0];

    float acc;
    if (map >= 0) {
        acc = matched_loss(map, base, sxv, syv, conf, a2, a3,
                           x1, x2, y1s, y2s, parea);
    } else {
        float cc = found ? 0.0f : conf;
        acc = cc * cc;
    }

    // ---------------- reduction (shuffle-based) -----------------------------
    float v = acc;
#pragma unroll
    for (int o = 16; o > 0; o >>= 1) v += __shfl_down_sync(0xffffffffu, v, o);
    if (lane == 0) wred[wrp] = v;
    __syncthreads();
    if (tid < 32) {
        float s = (tid < 8) ? wred[tid] : 0.0f;
#pragma unroll
        for (int o = 4; o > 0; o >>= 1) s += __shfl_down_sync(0xffffffffu, s, o);
        if (tid == 0) {
            g_partials[bid] = s;
            __threadfence();
            unsigned int r = atomicAdd(&g_count, 1u);
            s_last = (r == (unsigned)(kGrid - 1));
        }
    }
    __syncthreads();

    if (s_last) {
        float s = 0.0f;
        for (int p = tid; p < kGrid; p += 256) s += __ldcg(&g_partials[p]);
#pragma unroll
        for (int o = 16; o > 0; o >>= 1) s += __shfl_down_sync(0xffffffffu, s, o);
        if (lane == 0) wred[wrp] = s;
        __syncthreads();
        if (tid == 0) {
            float tot = 0.0f;
#pragma unroll
            for (int q = 0; q < 8; q++) tot += wred[q];
            loss[0] = tot;
            g_count = 0;
        }
        for (int p = 1 + tid; p < out_size; p += 256) loss[p] = 0.0f;
    }
}

extern "C" void kernel_launch(void* const* d_in, const int* in_sizes, int n_in,
                              void* d_out, int out_size) {
    const float* output = (const float*)d_in[0];
    const float* target = (const float*)d_in[1];
    k_fused<<<kGrid, 256>>>(output, target, (float*)d_out, out_size);
}